// round 6
// baseline (speedup 1.0000x reference)
#include <cuda_runtime.h>
#include <math_constants.h>
#include <cstdint>

#define B  4
#define N  16384
#define S  4096
#define C  256

#define SPAIRS (S / 2)          // 2048 key-pairs (64 KB smem)
#define QT     256              // threads per knn block
#define UNCOND 256              // pairs processed with unconditional inserts

// Final per-query weights + indices (allocation-free rule -> device globals)
__device__ float g_w[B * N * 3];
__device__ int   g_i[B * N * 3];

// ---------------------------------------------------------------------------
// f32x2 packed helpers
// ---------------------------------------------------------------------------
__device__ __forceinline__ uint64_t fma2_(uint64_t a, uint64_t b, uint64_t c) {
    uint64_t d;
    asm("fma.rn.f32x2 %0, %1, %2, %3;" : "=l"(d) : "l"(a), "l"(b), "l"(c));
    return d;
}
__device__ __forceinline__ uint64_t pack2_(float lo, float hi) {
    uint64_t d;
    asm("mov.b64 %0, {%1, %2};" : "=l"(d) : "f"(lo), "f"(hi));
    return d;
}
__device__ __forceinline__ void unpack2_(uint64_t v, float& lo, float& hi) {
    asm("mov.b64 {%0, %1}, %2;" : "=f"(lo), "=f"(hi) : "l"(v));
}

// Branch-free, SELF-GUARDING sorted-3 insert: if d >= d2 nothing changes.
// Strict < keeps earliest index on ties (matches jax.lax.top_k).
#define FLAT_INSERT(D0, D1, D2, I0, I1, I2, d, s) do {                    \
    const bool q0 = (d) < (D0);                                           \
    const bool q1 = (d) < (D1);                                           \
    const bool q2 = (d) < (D2);                                           \
    const float od1 = (D1); const int oi1 = (I1);                         \
    const float od0 = (D0); const int oi0 = (I0);                         \
    (D2) = q2 ? (q1 ? od1 : (d)) : (D2);                                  \
    (I2) = q2 ? (q1 ? oi1 : (s)) : (I2);                                  \
    (D1) = q1 ? (q0 ? od0 : (d)) : (D1);                                  \
    (I1) = q1 ? (q0 ? oi0 : (s)) : (I1);                                  \
    (D0) = q0 ? (d) : (D0);                                               \
    (I0) = q0 ? (s) : (I0);                                               \
} while (0)

// ---------------------------------------------------------------------------
// Phase 1: single-pass 3-NN, TWO queries per thread (A, B) packed in f32x2.
// Keys in smem as pairs: kp[2p] = {x0,x1 | y0,y1}, kp[2p+1] = {z0,z1 | kk0,kk1}.
// Dual coefficient orders give all 4 (query,key) distances per pair with
// 6 FFMA2 and 2 LDS.128 — crossbar traffic halved vs 1 query/thread.
// d' = kk - 2 q.k (qq dropped in-loop: top-k invariant; re-added for weights).
// ---------------------------------------------------------------------------
__global__ void __launch_bounds__(QT) knn_kernel(const float* __restrict__ q,
                                                 const float* __restrict__ k)
{
    extern __shared__ ulonglong2 kp[];   // SPAIRS*2 entries = 64 KB

    const int b  = blockIdx.y;
    const int nA = blockIdx.x * (QT * 2) + threadIdx.x;   // query A
    const int nB = nA + QT;                               // query B

    // Cooperative key load: packed pair layout + ||k||^2
    const float* kb = k + (size_t)b * S * 3;
    for (int p = threadIdx.x; p < SPAIRS; p += QT) {
        float x0 = kb[6 * p + 0], y0 = kb[6 * p + 1], z0 = kb[6 * p + 2];
        float x1 = kb[6 * p + 3], y1 = kb[6 * p + 4], z1 = kb[6 * p + 5];
        float w0 = fmaf(x0, x0, fmaf(y0, y0, z0 * z0));
        float w1 = fmaf(x1, x1, fmaf(y1, y1, z1 * z1));
        kp[2 * p]     = make_ulonglong2(pack2_(x0, x1), pack2_(y0, y1));
        kp[2 * p + 1] = make_ulonglong2(pack2_(z0, z1), pack2_(w0, w1));
    }
    __syncthreads();

    const float* qpA = q + ((size_t)b * N + nA) * 3;
    const float* qpB = q + ((size_t)b * N + nB) * 3;
    const float qxA = qpA[0], qyA = qpA[1], qzA = qpA[2];
    const float qxB = qpB[0], qyB = qpB[1], qzB = qpB[2];
    const float qqA = fmaf(qxA, qxA, fmaf(qyA, qyA, qzA * qzA));
    const float qqB = fmaf(qxB, qxB, fmaf(qyB, qyB, qzB * qzB));

    // AB-order and BA-order packed coefficients (registers only)
    const uint64_t cxAB = pack2_(-2.0f * qxA, -2.0f * qxB);
    const uint64_t cyAB = pack2_(-2.0f * qyA, -2.0f * qyB);
    const uint64_t czAB = pack2_(-2.0f * qzA, -2.0f * qzB);
    const uint64_t cxBA = pack2_(-2.0f * qxB, -2.0f * qxA);
    const uint64_t cyBA = pack2_(-2.0f * qyB, -2.0f * qyA);
    const uint64_t czBA = pack2_(-2.0f * qzB, -2.0f * qzA);

    float dA0 = CUDART_INF_F, dA1 = CUDART_INF_F, dA2 = CUDART_INF_F;
    float dB0 = CUDART_INF_F, dB1 = CUDART_INF_F, dB2 = CUDART_INF_F;
    int   iA0 = 0, iA1 = 0, iA2 = 0, iB0 = 0, iB1 = 0, iB2 = 0;

    // --- Startup span: inserts near-certain; skip the branch entirely ---
#pragma unroll 4
    for (int p = 0; p < UNCOND; ++p) {
        const ulonglong2 A = kp[2 * p];
        const ulonglong2 Z = kp[2 * p + 1];
        const uint64_t t1 = fma2_(cxAB, A.x, fma2_(cyAB, A.y, fma2_(czAB, Z.x, Z.y)));
        const uint64_t t2 = fma2_(cxBA, A.x, fma2_(cyBA, A.y, fma2_(czBA, Z.x, Z.y)));
        float a0, b1, b0, a1;
        unpack2_(t1, a0, b1);   // {d(A,k2p), d(B,k2p+1)}
        unpack2_(t2, b0, a1);   // {d(B,k2p), d(A,k2p+1)}
        FLAT_INSERT(dA0, dA1, dA2, iA0, iA1, iA2, a0, 2 * p);
        FLAT_INSERT(dA0, dA1, dA2, iA0, iA1, iA2, a1, 2 * p + 1);
        FLAT_INSERT(dB0, dB1, dB2, iB0, iB1, iB2, b0, 2 * p);
        FLAT_INSERT(dB0, dB1, dB2, iB0, iB1, iB2, b1, 2 * p + 1);
    }

    // --- Main span: rare branch; body = 4 self-guarded flat inserts ---
#pragma unroll 4
    for (int p = UNCOND; p < SPAIRS; ++p) {
        const ulonglong2 A = kp[2 * p];
        const ulonglong2 Z = kp[2 * p + 1];
        const uint64_t t1 = fma2_(cxAB, A.x, fma2_(cyAB, A.y, fma2_(czAB, Z.x, Z.y)));
        const uint64_t t2 = fma2_(cxBA, A.x, fma2_(cyBA, A.y, fma2_(czBA, Z.x, Z.y)));
        float a0, b1, b0, a1;
        unpack2_(t1, a0, b1);
        unpack2_(t2, b0, a1);
        if (fminf(a0, a1) < dA2 || fminf(b0, b1) < dB2) {
            FLAT_INSERT(dA0, dA1, dA2, iA0, iA1, iA2, a0, 2 * p);
            FLAT_INSERT(dA0, dA1, dA2, iA0, iA1, iA2, a1, 2 * p + 1);
            FLAT_INSERT(dB0, dB1, dB2, iB0, iB1, iB2, b0, 2 * p);
            FLAT_INSERT(dB0, dB1, dB2, iB0, iB1, iB2, b1, 2 * p + 1);
        }
    }

    // Weights: true distance = d' + qq per query
    {
        const float r0 = 1.0f / (dA0 + qqA + 1e-8f);
        const float r1 = 1.0f / (dA1 + qqA + 1e-8f);
        const float r2 = 1.0f / (dA2 + qqA + 1e-8f);
        const float inv = 1.0f / (r0 + r1 + r2);
        const int base = (b * N + nA) * 3;
        g_w[base + 0] = r0 * inv;  g_i[base + 0] = iA0;
        g_w[base + 1] = r1 * inv;  g_i[base + 1] = iA1;
        g_w[base + 2] = r2 * inv;  g_i[base + 2] = iA2;
    }
    {
        const float r0 = 1.0f / (dB0 + qqB + 1e-8f);
        const float r1 = 1.0f / (dB1 + qqB + 1e-8f);
        const float r2 = 1.0f / (dB2 + qqB + 1e-8f);
        const float inv = 1.0f / (r0 + r1 + r2);
        const int base = (b * N + nB) * 3;
        g_w[base + 0] = r0 * inv;  g_i[base + 0] = iB0;
        g_w[base + 1] = r1 * inv;  g_i[base + 1] = iB1;
        g_w[base + 2] = r2 * inv;  g_i[base + 2] = iB2;
    }
}

// ---------------------------------------------------------------------------
// Phase 2: weighted gather (float4 rows of v) + transpose to out[b][c][n].
// NQ=16 -> 17 KB smem -> 8 blocks/SM.
// ---------------------------------------------------------------------------
#define NQ 16

__global__ void __launch_bounds__(256) gather_kernel(const float* __restrict__ v,
                                                     float* __restrict__ out)
{
    __shared__ float buf[NQ][C + 4];   // rows 16B-aligned for STS.128
    __shared__ float w[NQ * 3];
    __shared__ int   id[NQ * 3];

    const int b   = blockIdx.y;
    const int n0  = blockIdx.x * NQ;
    const int tid = threadIdx.x;       // 256 threads

    if (tid < NQ * 3) {
        const int base = (b * N + n0) * 3;
        w[tid]  = g_w[base + tid];
        id[tid] = g_i[base + tid];
    }
    __syncthreads();

    const float4* vb4 = (const float4*)(v + (size_t)b * S * C);
    const int c4 = tid & 63;          // float4 channel slot (64 per row)
    const int qo = tid >> 6;          // 4 queries per iteration

#pragma unroll
    for (int qb = 0; qb < NQ; qb += 4) {
        const int ql = qb + qo;
        const int   j0 = id[ql * 3 + 0], j1 = id[ql * 3 + 1], j2 = id[ql * 3 + 2];
        const float w0 = w[ql * 3 + 0],  w1 = w[ql * 3 + 1],  w2 = w[ql * 3 + 2];
        const float4 a0 = vb4[j0 * 64 + c4];
        const float4 a1 = vb4[j1 * 64 + c4];
        const float4 a2 = vb4[j2 * 64 + c4];
        float4 r;
        r.x = fmaf(w0, a0.x, fmaf(w1, a1.x, w2 * a2.x));
        r.y = fmaf(w0, a0.y, fmaf(w1, a1.y, w2 * a2.y));
        r.z = fmaf(w0, a0.z, fmaf(w1, a1.z, w2 * a2.z));
        r.w = fmaf(w0, a0.w, fmaf(w1, a1.w, w2 * a2.w));
        *(float4*)&buf[ql][c4 * 4] = r;   // STS.128
    }
    __syncthreads();

    // Transposed write: each warp covers 2 channels per iter (16 n per half-warp)
    const int lane = tid & 31;
    const int warp = tid >> 5;
    const int nloc = lane & 15;
    const int csub = lane >> 4;
    float* ob = out + (size_t)b * C * N + n0;
#pragma unroll
    for (int it = 0; it < 16; ++it) {
        const int c = it * 16 + warp * 2 + csub;
        ob[c * N + nloc] = buf[nloc][c];
    }
}

// ---------------------------------------------------------------------------
extern "C" void kernel_launch(void* const* d_in, const int* in_sizes, int n_in,
                              void* d_out, int out_size)
{
    const float* q = (const float*)d_in[0];   // (B, N, 3)
    const float* k = (const float*)d_in[1];   // (B, S, 3)
    const float* v = (const float*)d_in[2];   // (B, S, C)
    float* out = (float*)d_out;               // (B, C, N)

    static_assert(SPAIRS * 2 * sizeof(ulonglong2) == 65536, "smem size");
    cudaFuncSetAttribute(knn_kernel,
                         cudaFuncAttributeMaxDynamicSharedMemorySize, 65536);

    dim3 g1(N / (QT * 2), B);                 // 32 x 4 = 128 blocks
    knn_kernel<<<g1, QT, 65536>>>(q, k);

    dim3 g2(N / NQ, B);                       // 1024 x 4 = 4096 blocks
    gather_kernel<<<g2, 256>>>(v, out);
}